// round 9
// baseline (speedup 1.0000x reference)
#include <cuda_runtime.h>
#include <cstdint>

#define CCH 64
#define HH 128
#define WW 128
#define NBATCH 32
#define KW 7
#define NTHREADS 256
#define TOTAL_ROWS (NBATCH * HH)
#define HW (HH * WW)

// smem layout (bytes)
#define B_BYTES (KW * 8 * 4 * 32 * 16)        // 114688: [j][kt][ntp][lane] uint4
#define TOFF B_BYTES
#define T_STRIDE 68                            // uint32 per T row (64 ci + 4 pad)
#define T_ROWS 146                             // rows 0..145 (reads reach 145)
#define T_BYTES (T_ROWS * T_STRIDE * 4)        // 39712
#define T4OFF (TOFF + 2 * T_BYTES)             // 194112
#define BUF_STRIDE 132                         // floats per co row (128 + 4 pad)
#define BUF_BYTES (CCH * BUF_STRIDE * 4)       // 33792
#define SMEM_DYN (T4OFF + BUF_BYTES)           // 227904

__device__ __forceinline__ uint32_t f2tf32(float f) {
    uint32_t r;
    asm("cvt.rna.tf32.f32 %0, %1;" : "=r"(r) : "f"(f));
    return r;
}

__device__ __forceinline__ void mma_tf32(float* d,
                                         uint32_t a0, uint32_t a1,
                                         uint32_t a2, uint32_t a3,
                                         uint32_t b0, uint32_t b1) {
    asm volatile(
        "mma.sync.aligned.m16n8k8.row.col.f32.tf32.tf32.f32 "
        "{%0,%1,%2,%3}, {%4,%5,%6,%7}, {%8,%9}, {%0,%1,%2,%3};"
        : "+f"(d[0]), "+f"(d[1]), "+f"(d[2]), "+f"(d[3])
        : "r"(a0), "r"(a1), "r"(a2), "r"(a3), "r"(b0), "r"(b1));
}

// Stage x[n][:, h, :] -> T[buf] as tf32, transposed [w+9][ci].
// Generic over a contiguous id range [0, nthr).
__device__ __forceinline__ void stage_T(char* smem, const float* __restrict__ x,
                                        int n, int h, int buf, int id, int nthr) {
    uint32_t* Tb = (uint32_t*)(smem + TOFF + buf * T_BYTES);
    const float* xrow = x + ((size_t)(n * CCH) * HH + h) * WW;
    const int ci = id & 63;
    const int w0 = id >> 6;
    const int wstep = nthr >> 6;
    #pragma unroll 4
    for (int wg = w0; wg < 32; wg += wstep) {
        const float4 v = __ldg((const float4*)(xrow + (size_t)ci * HW + wg * 4));
        uint32_t* dst = Tb + (4 * wg + 9) * T_STRIDE + ci;
        dst[0 * T_STRIDE] = f2tf32(v.x);
        dst[1 * T_STRIDE] = f2tf32(v.y);
        dst[2 * T_STRIDE] = f2tf32(v.z);
        dst[3 * T_STRIDE] = f2tf32(v.w);
    }
}

extern "C" __global__ void __launch_bounds__(NTHREADS, 1)
fused_conv_mma_kernel(const float* __restrict__ x,
                      const float* __restrict__ wconv,
                      const float* __restrict__ p4,
                      float* __restrict__ out) {
    extern __shared__ char smem[];
    const int tid = threadIdx.x;
    const int lane = tid & 31;
    const int warp = tid >> 5;
    const bool is_mma = (warp < 4);
    const int mwarp = warp & 3;       // m-stripe for MMA warps; epi sub-id for others

    // ---- one-time: pack B fragments [j][kt][ntp][lane] = uint4 ----
    for (int idx = tid; idx < KW * 8 * 4 * 32; idx += NTHREADS) {
        const int t   = idx & 31;
        const int ntp = (idx >> 5) & 3;
        const int kt  = (idx >> 7) & 7;
        const int j   = idx >> 10;
        const int n_in = t >> 2;
        const int k_in = t & 3;
        const int ci0 = kt * 8 + k_in, ci1 = ci0 + 4;
        const int coA = 16 * ntp + n_in, coB = coA + 8;
        uint4 v;
        v.x = f2tf32(__ldg(wconv + (coA * CCH + ci0) * KW + j));
        v.y = f2tf32(__ldg(wconv + (coA * CCH + ci1) * KW + j));
        v.z = f2tf32(__ldg(wconv + (coB * CCH + ci0) * KW + j));
        v.w = f2tf32(__ldg(wconv + (coB * CCH + ci1) * KW + j));
        ((uint4*)smem)[idx] = v;
    }
    // zero both T buffers (pad rows stay zero forever)
    for (int i = tid; i < 2 * T_ROWS * T_STRIDE; i += NTHREADS)
        ((uint32_t*)(smem + TOFF))[i] = 0;

    const float p40 = __ldg(p4 + 0), p41 = __ldg(p4 + 1), p42 = __ldg(p4 + 2);

    __syncthreads();
    int row = blockIdx.x;
    if (row < TOTAL_ROWS)
        stage_T(smem, x, row >> 7, row & (HH - 1), 0, tid, NTHREADS);
    __syncthreads();

    const uint4* Bfr = (const uint4*)smem;
    float* t4buf = (float*)(smem + T4OFF);
    int buf = 0;

    while (row < TOTAL_ROWS) {
        const int n = row >> 7;
        const int h = row & (HH - 1);
        const float* xb = x + (size_t)n * CCH * HW;
        float* ob = out + (size_t)n * CCH * HW;

        float acc[2][8][4];

        // ================= PHASE 1 =================
        if (is_mma) {
            // conv[w][co] for m-stripe mwarp, all 64 co
            #pragma unroll
            for (int mt = 0; mt < 2; ++mt)
                #pragma unroll
                for (int nt = 0; nt < 8; ++nt)
                    #pragma unroll
                    for (int q = 0; q < 4; ++q) acc[mt][nt][q] = 0.0f;

            const uint32_t* Tb = (const uint32_t*)(smem + TOFF + buf * T_BYTES);
            const int rbase = mwarp * 32 + (lane >> 2);
            const int cbase = lane & 3;
            #pragma unroll 1
            for (int j = 0; j < KW; ++j) {
                const uint32_t* Trow = Tb + (rbase + 3 * j) * T_STRIDE + cbase;
                const uint4* Bj = Bfr + j * 1024 + lane;
                #pragma unroll
                for (int kt = 0; kt < 8; ++kt) {
                    const uint32_t* Tc = Trow + kt * 8;
                    const uint32_t a0 = Tc[0];
                    const uint32_t a1 = Tc[8 * T_STRIDE];
                    const uint32_t a2 = Tc[4];
                    const uint32_t a3 = Tc[8 * T_STRIDE + 4];
                    const uint32_t a4 = Tc[16 * T_STRIDE];
                    const uint32_t a5 = Tc[24 * T_STRIDE];
                    const uint32_t a6 = Tc[16 * T_STRIDE + 4];
                    const uint32_t a7 = Tc[24 * T_STRIDE + 4];
                    const uint4 b01 = Bj[kt * 128 + 0 * 32];
                    const uint4 b23 = Bj[kt * 128 + 1 * 32];
                    const uint4 b45 = Bj[kt * 128 + 2 * 32];
                    const uint4 b67 = Bj[kt * 128 + 3 * 32];
                    mma_tf32(acc[0][0], a0, a1, a2, a3, b01.x, b01.y);
                    mma_tf32(acc[0][1], a0, a1, a2, a3, b01.z, b01.w);
                    mma_tf32(acc[0][2], a0, a1, a2, a3, b23.x, b23.y);
                    mma_tf32(acc[0][3], a0, a1, a2, a3, b23.z, b23.w);
                    mma_tf32(acc[0][4], a0, a1, a2, a3, b45.x, b45.y);
                    mma_tf32(acc[0][5], a0, a1, a2, a3, b45.z, b45.w);
                    mma_tf32(acc[0][6], a0, a1, a2, a3, b67.x, b67.y);
                    mma_tf32(acc[0][7], a0, a1, a2, a3, b67.z, b67.w);
                    mma_tf32(acc[1][0], a4, a5, a6, a7, b01.x, b01.y);
                    mma_tf32(acc[1][1], a4, a5, a6, a7, b01.z, b01.w);
                    mma_tf32(acc[1][2], a4, a5, a6, a7, b23.x, b23.y);
                    mma_tf32(acc[1][3], a4, a5, a6, a7, b23.z, b23.w);
                    mma_tf32(acc[1][4], a4, a5, a6, a7, b45.x, b45.y);
                    mma_tf32(acc[1][5], a4, a5, a6, a7, b45.z, b45.w);
                    mma_tf32(acc[1][6], a4, a5, a6, a7, b67.x, b67.y);
                    mma_tf32(acc[1][7], a4, a5, a6, a7, b67.z, b67.w);
                }
            }
        } else {
            // ---- t4(row) into t4buf (coalesced LDG, hidden under MMA) ----
            const int hm1 = (h - 1 + HH) & (HH - 1);
            const int r0 = hm1 - 2, r2 = hm1 + 2;
            const bool has0 = (r0 >= 0), has2 = (r2 < HH);
            const int e = mwarp;     // 0..3
            #pragma unroll 1
            for (int i = 0; i < 16; ++i) {
                const int co = e + 4 * i;
                const float* xc = xb + (size_t)co * HW;
                #pragma unroll
                for (int k = 0; k < 4; ++k) {
                    const int win = lane + 32 * k;
                    float t4v = p41 * __ldg(xc + hm1 * WW + win);
                    if (has0) t4v = fmaf(p40, __ldg(xc + r0 * WW + win), t4v);
                    if (has2) t4v = fmaf(p42, __ldg(xc + r2 * WW + win), t4v);
                    t4buf[co * BUF_STRIDE + ((win - 2) & (WW - 1))] = t4v;
                }
            }
            // ---- stage next row into T[buf^1] ----
            const int nrow = row + gridDim.x;
            if (nrow < TOTAL_ROWS)
                stage_T(smem, x, nrow >> 7, nrow & (HH - 1), buf ^ 1,
                        tid - 128, 128);
        }

        __syncthreads();

        // ================= PHASE 2 =================
        if (is_mma) {
            #pragma unroll
            for (int nt = 0; nt < 8; ++nt) {
                #pragma unroll
                for (int mt = 0; mt < 2; ++mt)
                    #pragma unroll
                    for (int half = 0; half < 2; ++half)
                        #pragma unroll
                        for (int q = 0; q < 2; ++q) {
                            const int w = mwarp * 32 + mt * 16 + (lane >> 2) + half * 8;
                            const int co = nt * 8 + 2 * (lane & 3) + q;
                            const float t4v = t4buf[co * BUF_STRIDE + w];
                            const float xv = __ldg(xb + (size_t)co * HW + h * WW + w);
                            ob[(size_t)co * HW + h * WW + w] =
                                (xv + acc[mt][nt][half * 2 + q]) * t4v;
                        }
            }
        }

        __syncthreads();
        buf ^= 1;
        row += gridDim.x;
    }
}

extern "C" void kernel_launch(void* const* d_in, const int* in_sizes, int n_in,
                              void* d_out, int out_size) {
    const float* x     = (const float*)d_in[0];
    const float* wconv = (const float*)d_in[1];
    const float* p4    = (const float*)d_in[2];
    float* out         = (float*)d_out;

    (void)in_sizes; (void)n_in; (void)out_size;

    cudaFuncSetAttribute(fused_conv_mma_kernel,
                         cudaFuncAttributeMaxDynamicSharedMemorySize, SMEM_DYN);

    int dev = 0, sms = 148;
    cudaGetDevice(&dev);
    cudaDeviceGetAttribute(&sms, cudaDevAttrMultiProcessorCount, dev);

    fused_conv_mma_kernel<<<sms, NTHREADS, SMEM_DYN>>>(x, wconv, p4, out);
}

// round 10
// speedup vs baseline: 2.2951x; 2.2951x over previous
#include <cuda_runtime.h>
#include <cstdint>

#define CCH 64
#define HH 128
#define WW 128
#define NBATCH 32
#define KW 7
#define NTHREADS 512
#define TOTAL_ROWS (NBATCH * HH)
#define HW (HH * WW)

// smem layout (bytes)
#define B_BYTES (KW * 8 * 4 * 32 * 16)        // 114688: [j][kt][ntp][lane] uint4
#define TOFF B_BYTES
#define T_STRIDE 68                            // uint32 per T row (64 ci + 4 pad)
#define T_ROWS 152
#define T_BYTES (T_ROWS * T_STRIDE * 4)        // 41344
#define CONVOFF (TOFF + T_BYTES)
#define BUF_STRIDE 132                         // floats per co row (128 + 4 pad)
#define BUF_BYTES (CCH * BUF_STRIDE * 4)       // 33792
#define T4OFF (CONVOFF + BUF_BYTES)
#define SMEM_DYN (T4OFF + BUF_BYTES)           // 223616

__device__ __forceinline__ uint32_t f2tf32(float f) {
    uint32_t r;
    asm("cvt.rna.tf32.f32 %0, %1;" : "=r"(r) : "f"(f));
    return r;
}

__device__ __forceinline__ void mma_tf32(float* d,
                                         uint32_t a0, uint32_t a1,
                                         uint32_t a2, uint32_t a3,
                                         uint32_t b0, uint32_t b1) {
    asm volatile(
        "mma.sync.aligned.m16n8k8.row.col.f32.tf32.tf32.f32 "
        "{%0,%1,%2,%3}, {%4,%5,%6,%7}, {%8,%9}, {%0,%1,%2,%3};"
        : "+f"(d[0]), "+f"(d[1]), "+f"(d[2]), "+f"(d[3])
        : "r"(a0), "r"(a1), "r"(a2), "r"(a3), "r"(b0), "r"(b1));
}

// Stage x[n][:, h, :] -> T as tf32, transposed [w+9][ci].
__device__ __forceinline__ void stage_T(char* smem, const float* __restrict__ x,
                                        int n, int h) {
    const int tid = threadIdx.x;
    uint32_t* Tb = (uint32_t*)(smem + TOFF);
    const float* xrow = x + ((size_t)(n * CCH) * HH + h) * WW;
    const int ci = tid & 63;
    const int w0 = tid >> 6;                   // 0..7
    #pragma unroll
    for (int it = 0; it < 4; ++it) {
        const int wg = w0 + 8 * it;            // 0..31
        const float4 v = __ldg((const float4*)(xrow + (size_t)ci * HW + wg * 4));
        uint32_t* dst = Tb + (4 * wg + 9) * T_STRIDE + ci;
        dst[0 * T_STRIDE] = f2tf32(v.x);
        dst[1 * T_STRIDE] = f2tf32(v.y);
        dst[2 * T_STRIDE] = f2tf32(v.z);
        dst[3 * T_STRIDE] = f2tf32(v.w);
    }
}

extern "C" __global__ void __launch_bounds__(NTHREADS, 1)
fused_conv_mma_kernel(const float* __restrict__ x,
                      const float* __restrict__ wconv,
                      const float* __restrict__ p4,
                      float* __restrict__ out) {
    extern __shared__ char smem[];
    const int tid = threadIdx.x;
    const int lane = tid & 31;
    const int warp = tid >> 5;                 // 0..15
    const int g = warp >> 3;                   // n-half (co 0..31 / 32..63)
    const int mw = warp & 7;                   // m-stripe (16 w rows)

    // ---- one-time: pack B fragments [j][kt][ntp][lane] = uint4 ----
    for (int idx = tid; idx < KW * 8 * 4 * 32; idx += NTHREADS) {
        const int t   = idx & 31;
        const int ntp = (idx >> 5) & 3;
        const int kt  = (idx >> 7) & 7;
        const int j   = idx >> 10;
        const int n_in = t >> 2;
        const int k_in = t & 3;
        const int ci0 = kt * 8 + k_in, ci1 = ci0 + 4;
        const int coA = 16 * ntp + n_in, coB = coA + 8;
        uint4 v;
        v.x = f2tf32(__ldg(wconv + (coA * CCH + ci0) * KW + j));
        v.y = f2tf32(__ldg(wconv + (coA * CCH + ci1) * KW + j));
        v.z = f2tf32(__ldg(wconv + (coB * CCH + ci0) * KW + j));
        v.w = f2tf32(__ldg(wconv + (coB * CCH + ci1) * KW + j));
        ((uint4*)smem)[idx] = v;
    }
    // zero T (pad rows stay zero forever)
    for (int i = tid; i < T_ROWS * T_STRIDE; i += NTHREADS)
        ((uint32_t*)(smem + TOFF))[i] = 0;

    const float p40 = __ldg(p4 + 0), p41 = __ldg(p4 + 1), p42 = __ldg(p4 + 2);

    __syncthreads();
    int row = blockIdx.x;
    if (row < TOTAL_ROWS) stage_T(smem, x, row >> 7, row & (HH - 1));
    __syncthreads();

    const uint4* Bfr = (const uint4*)smem;
    float* convbuf = (float*)(smem + CONVOFF);
    float* t4buf   = (float*)(smem + T4OFF);

    while (row < TOTAL_ROWS) {
        const int n = row >> 7;
        const int h = row & (HH - 1);
        const float* xb = x + (size_t)n * CCH * HW;
        float* ob = out + (size_t)n * CCH * HW;
        const int hm1 = (h - 1 + HH) & (HH - 1);
        const int r0 = hm1 - 2, r2 = hm1 + 2;
        const bool has0 = (r0 >= 0), has2 = (r2 < HH);

        // ---- MMA: conv[w][co] for m-stripe mw (16 rows), co-half g ----
        float acc[4][4];
        #pragma unroll
        for (int nt = 0; nt < 4; ++nt)
            #pragma unroll
            for (int q = 0; q < 4; ++q) acc[nt][q] = 0.0f;

        {
            const uint32_t* Tb = (const uint32_t*)(smem + TOFF);
            const int rbase = mw * 16 + (lane >> 2);
            const int cbase = lane & 3;
            #pragma unroll 1
            for (int j = 0; j < KW; ++j) {
                const uint32_t* Trow = Tb + (rbase + 3 * j) * T_STRIDE + cbase;
                const uint4* Bj = Bfr + j * 1024 + 64 * g + lane;
                #pragma unroll
                for (int kt = 0; kt < 8; ++kt) {
                    const uint32_t* Tc = Trow + kt * 8;
                    const uint32_t a0 = Tc[0];
                    const uint32_t a1 = Tc[8 * T_STRIDE];
                    const uint32_t a2 = Tc[4];
                    const uint32_t a3 = Tc[8 * T_STRIDE + 4];
                    const uint4 b01 = Bj[kt * 128];
                    const uint4 b23 = Bj[kt * 128 + 32];
                    mma_tf32(acc[0], a0, a1, a2, a3, b01.x, b01.y);
                    mma_tf32(acc[1], a0, a1, a2, a3, b01.z, b01.w);
                    mma_tf32(acc[2], a0, a1, a2, a3, b23.x, b23.y);
                    mma_tf32(acc[3], a0, a1, a2, a3, b23.z, b23.w);
                }
            }
        }

        // ---- dump accumulators to convbuf[co][w] ----
        #pragma unroll
        for (int half = 0; half < 2; ++half) {
            const int w = mw * 16 + half * 8 + (lane >> 2);
            #pragma unroll
            for (int nt = 0; nt < 4; ++nt)
                #pragma unroll
                for (int q = 0; q < 2; ++q) {
                    const int co = 32 * g + nt * 8 + 2 * (lane & 3) + q;
                    convbuf[co * BUF_STRIDE + w] = acc[nt][half * 2 + q];
                }
        }

        // ---- cooperative t4 into t4buf[co][w] (coalesced LDG) ----
        #pragma unroll 1
        for (int i = 0; i < 4; ++i) {
            const int co = warp + 16 * i;
            const float* xc = xb + (size_t)co * HW;
            #pragma unroll
            for (int k = 0; k < 4; ++k) {
                const int win = lane + 32 * k;
                float t4v = p41 * __ldg(xc + hm1 * WW + win);
                if (has0) t4v = fmaf(p40, __ldg(xc + r0 * WW + win), t4v);
                if (has2) t4v = fmaf(p42, __ldg(xc + r2 * WW + win), t4v);
                t4buf[co * BUF_STRIDE + ((win - 2) & (WW - 1))] = t4v;
            }
        }

        __syncthreads();

        // ---- stage next row (overlaps out-phase latency) ----
        const int nrow = row + gridDim.x;
        if (nrow < TOTAL_ROWS) stage_T(smem, x, nrow >> 7, nrow & (HH - 1));

        // ---- out phase: coalesced float4 ----
        #pragma unroll 1
        for (int i = 0; i < 4; ++i) {
            const int co = warp + 16 * i;
            const float4 cv = *(const float4*)(convbuf + co * BUF_STRIDE + 4 * lane);
            const float4 tv = *(const float4*)(t4buf + co * BUF_STRIDE + 4 * lane);
            const float4 xv = __ldg((const float4*)(xb + (size_t)co * HW + h * WW + 4 * lane));
            float4 ov;
            ov.x = (xv.x + cv.x) * tv.x;
            ov.y = (xv.y + cv.y) * tv.y;
            ov.z = (xv.z + cv.z) * tv.z;
            ov.w = (xv.w + cv.w) * tv.w;
            *(float4*)(ob + (size_t)co * HW + h * WW + 4 * lane) = ov;
        }

        __syncthreads();   // T staged + convbuf/t4buf reads done
        row = nrow;
    }
}

extern "C" void kernel_launch(void* const* d_in, const int* in_sizes, int n_in,
                              void* d_out, int out_size) {
    const float* x     = (const float*)d_in[0];
    const float* wconv = (const float*)d_in[1];
    const float* p4    = (const float*)d_in[2];
    float* out         = (float*)d_out;

    (void)in_sizes; (void)n_in; (void)out_size;

    cudaFuncSetAttribute(fused_conv_mma_kernel,
                         cudaFuncAttributeMaxDynamicSharedMemorySize, SMEM_DYN);

    int dev = 0, sms = 148;
    cudaGetDevice(&dev);
    cudaDeviceGetAttribute(&sms, cudaDevAttrMultiProcessorCount, dev);

    fused_conv_mma_kernel<<<sms, NTHREADS, SMEM_DYN>>>(x, wconv, p4, out);
}

// round 11
// speedup vs baseline: 2.7401x; 1.1939x over previous
#include <cuda_runtime.h>
#include <cstdint>

#define CCH 64
#define HH 128
#define WW 128
#define NBATCH 32
#define KW 7
#define NTHREADS 1024
#define TOTAL_ROWS (NBATCH * HH)
#define HW (HH * WW)

// smem layout (bytes)
#define B_BYTES (KW * 8 * 4 * 32 * 16)        // 114688: [j][kt][ntp][lane] uint4
#define TOFF B_BYTES
#define T_STRIDE 68                            // uint32 per T row (64 ci + 4 pad)
#define T_ROWS 152
#define T_BYTES (T_ROWS * T_STRIDE * 4)        // 41344
#define CONVOFF (TOFF + T_BYTES)
#define BUF_STRIDE 132                         // floats per co row (128 + 4 pad)
#define BUF_BYTES (CCH * BUF_STRIDE * 4)       // 33792
#define T4OFF (CONVOFF + BUF_BYTES)
#define SMEM_DYN (T4OFF + BUF_BYTES)           // 223616

__device__ __forceinline__ uint32_t f2tf32(float f) {
    uint32_t r;
    asm("cvt.rna.tf32.f32 %0, %1;" : "=r"(r) : "f"(f));
    return r;
}

__device__ __forceinline__ void mma_tf32(float* d,
                                         uint32_t a0, uint32_t a1,
                                         uint32_t a2, uint32_t a3,
                                         uint32_t b0, uint32_t b1) {
    asm volatile(
        "mma.sync.aligned.m16n8k8.row.col.f32.tf32.tf32.f32 "
        "{%0,%1,%2,%3}, {%4,%5,%6,%7}, {%8,%9}, {%0,%1,%2,%3};"
        : "+f"(d[0]), "+f"(d[1]), "+f"(d[2]), "+f"(d[3])
        : "r"(a0), "r"(a1), "r"(a2), "r"(a3), "r"(b0), "r"(b1));
}

// Stage x[n][:, h, :] -> T as tf32, transposed [w+9][ci].
__device__ __forceinline__ void stage_T(char* smem, const float* __restrict__ x,
                                        int n, int h) {
    const int tid = threadIdx.x;
    uint32_t* Tb = (uint32_t*)(smem + TOFF);
    const float* xrow = x + ((size_t)(n * CCH) * HH + h) * WW;
    const int ci = tid & 63;
    const int w0 = tid >> 6;                   // 0..15
    #pragma unroll
    for (int it = 0; it < 2; ++it) {
        const int wg = w0 + 16 * it;           // 0..31
        const float4 v = __ldg((const float4*)(xrow + (size_t)ci * HW + wg * 4));
        uint32_t* dst = Tb + (4 * wg + 9) * T_STRIDE + ci;
        dst[0 * T_STRIDE] = f2tf32(v.x);
        dst[1 * T_STRIDE] = f2tf32(v.y);
        dst[2 * T_STRIDE] = f2tf32(v.z);
        dst[3 * T_STRIDE] = f2tf32(v.w);
    }
}

extern "C" __global__ void __launch_bounds__(NTHREADS, 1)
fused_conv_mma_kernel(const float* __restrict__ x,
                      const float* __restrict__ wconv,
                      const float* __restrict__ p4,
                      float* __restrict__ out) {
    extern __shared__ char smem[];
    const int tid = threadIdx.x;
    const int lane = tid & 31;
    const int warp = tid >> 5;                 // 0..31
    const int g2 = warp >> 3;                  // n-quarter (co 16*g2 .. 16*g2+15)
    const int mw = warp & 7;                   // m-stripe (16 w rows)

    // ---- one-time: pack B fragments [j][kt][ntp][lane] = uint4 ----
    for (int idx = tid; idx < KW * 8 * 4 * 32; idx += NTHREADS) {
        const int t   = idx & 31;
        const int ntp = (idx >> 5) & 3;
        const int kt  = (idx >> 7) & 7;
        const int j   = idx >> 10;
        const int n_in = t >> 2;
        const int k_in = t & 3;
        const int ci0 = kt * 8 + k_in, ci1 = ci0 + 4;
        const int coA = 16 * ntp + n_in, coB = coA + 8;
        uint4 v;
        v.x = f2tf32(__ldg(wconv + (coA * CCH + ci0) * KW + j));
        v.y = f2tf32(__ldg(wconv + (coA * CCH + ci1) * KW + j));
        v.z = f2tf32(__ldg(wconv + (coB * CCH + ci0) * KW + j));
        v.w = f2tf32(__ldg(wconv + (coB * CCH + ci1) * KW + j));
        ((uint4*)smem)[idx] = v;
    }
    // zero T (pad rows stay zero forever)
    for (int i = tid; i < T_ROWS * T_STRIDE; i += NTHREADS)
        ((uint32_t*)(smem + TOFF))[i] = 0;

    const float p40 = __ldg(p4 + 0), p41 = __ldg(p4 + 1), p42 = __ldg(p4 + 2);

    __syncthreads();
    int row = blockIdx.x;
    if (row < TOTAL_ROWS) stage_T(smem, x, row >> 7, row & (HH - 1));
    __syncthreads();

    const uint4* Bfr = (const uint4*)smem;
    float* convbuf = (float*)(smem + CONVOFF);
    float* t4buf   = (float*)(smem + T4OFF);

    while (row < TOTAL_ROWS) {
        const int n = row >> 7;
        const int h = row & (HH - 1);
        const float* xb = x + (size_t)n * CCH * HW;
        float* ob = out + (size_t)n * CCH * HW;
        const int hm1 = (h - 1 + HH) & (HH - 1);
        const int r0 = hm1 - 2, r2 = hm1 + 2;
        const bool has0 = (r0 >= 0), has2 = (r2 < HH);

        // ---- MMA: conv[w][co] for m-stripe mw (16 rows), n-quarter g2 ----
        float acc[2][4];
        #pragma unroll
        for (int nt = 0; nt < 2; ++nt)
            #pragma unroll
            for (int q = 0; q < 4; ++q) acc[nt][q] = 0.0f;

        {
            const uint32_t* Tb = (const uint32_t*)(smem + TOFF);
            const int rbase = mw * 16 + (lane >> 2);
            const int cbase = lane & 3;
            #pragma unroll 1
            for (int j = 0; j < KW; ++j) {
                const uint32_t* Trow = Tb + (rbase + 3 * j) * T_STRIDE + cbase;
                const uint4* Bj = Bfr + j * 1024 + 32 * g2 + lane;
                #pragma unroll
                for (int kt = 0; kt < 8; ++kt) {
                    const uint32_t* Tc = Trow + kt * 8;
                    const uint32_t a0 = Tc[0];
                    const uint32_t a1 = Tc[8 * T_STRIDE];
                    const uint32_t a2 = Tc[4];
                    const uint32_t a3 = Tc[8 * T_STRIDE + 4];
                    const uint4 b01 = Bj[kt * 128];
                    mma_tf32(acc[0], a0, a1, a2, a3, b01.x, b01.y);
                    mma_tf32(acc[1], a0, a1, a2, a3, b01.z, b01.w);
                }
            }
        }

        // ---- dump accumulators to convbuf[co][w] ----
        #pragma unroll
        for (int half = 0; half < 2; ++half) {
            const int w = mw * 16 + half * 8 + (lane >> 2);
            #pragma unroll
            for (int nt = 0; nt < 2; ++nt)
                #pragma unroll
                for (int q = 0; q < 2; ++q) {
                    const int co = 16 * g2 + nt * 8 + 2 * (lane & 3) + q;
                    convbuf[co * BUF_STRIDE + w] = acc[nt][half * 2 + q];
                }
        }

        // ---- cooperative t4 into t4buf[co][w] (coalesced LDG) ----
        #pragma unroll
        for (int i = 0; i < 2; ++i) {
            const int co = warp + 32 * i;
            const float* xc = xb + (size_t)co * HW;
            #pragma unroll
            for (int k = 0; k < 4; ++k) {
                const int win = lane + 32 * k;
                float t4v = p41 * __ldg(xc + hm1 * WW + win);
                if (has0) t4v = fmaf(p40, __ldg(xc + r0 * WW + win), t4v);
                if (has2) t4v = fmaf(p42, __ldg(xc + r2 * WW + win), t4v);
                t4buf[co * BUF_STRIDE + ((win - 2) & (WW - 1))] = t4v;
            }
        }

        __syncthreads();

        // ---- stage next row (overlaps out-phase latency) ----
        const int nrow = row + gridDim.x;
        if (nrow < TOTAL_ROWS) stage_T(smem, x, nrow >> 7, nrow & (HH - 1));

        // ---- out phase: coalesced float4 ----
        #pragma unroll
        for (int i = 0; i < 2; ++i) {
            const int co = warp + 32 * i;
            const float4 cv = *(const float4*)(convbuf + co * BUF_STRIDE + 4 * lane);
            const float4 tv = *(const float4*)(t4buf + co * BUF_STRIDE + 4 * lane);
            const float4 xv = __ldg((const float4*)(xb + (size_t)co * HW + h * WW + 4 * lane));
            float4 ov;
            ov.x = (xv.x + cv.x) * tv.x;
            ov.y = (xv.y + cv.y) * tv.y;
            ov.z = (xv.z + cv.z) * tv.z;
            ov.w = (xv.w + cv.w) * tv.w;
            *(float4*)(ob + (size_t)co * HW + h * WW + 4 * lane) = ov;
        }

        __syncthreads();   // T staged + convbuf/t4buf reads done
        row = nrow;
    }
}

extern "C" void kernel_launch(void* const* d_in, const int* in_sizes, int n_in,
                              void* d_out, int out_size) {
    const float* x     = (const float*)d_in[0];
    const float* wconv = (const float*)d_in[1];
    const float* p4    = (const float*)d_in[2];
    float* out         = (float*)d_out;

    (void)in_sizes; (void)n_in; (void)out_size;

    cudaFuncSetAttribute(fused_conv_mma_kernel,
                         cudaFuncAttributeMaxDynamicSharedMemorySize, SMEM_DYN);

    int dev = 0, sms = 148;
    cudaGetDevice(&dev);
    cudaDeviceGetAttribute(&sms, cudaDevAttrMultiProcessorCount, dev);

    fused_conv_mma_kernel<<<sms, NTHREADS, SMEM_DYN>>>(x, wconv, p4, out);
}